// round 16
// baseline (speedup 1.0000x reference)
#include <cuda_runtime.h>
#include <cuda_bf16.h>
#include <cstdint>
#include <cstddef>

#define BATCH 2048
#define T_STEPS 128
#define HID 512
#define NCMD 3
#define NOUT 5
#define G3 1536

typedef __nv_bfloat16 bf16;

#define MT 128
#define JT 32
#define NT 96
#define KC 16
#define NCH 32
#define KPAD 24
#define AB (MT * KPAD * 2)               // 6144
#define BB (NT * KPAD * 2)               // 4608
#define STG (2 * AB + 2 * BB)            // 21504
#define NST 3
#define STAGES (NST * STG)               // 64512
#define SST 97
#define S_BYTES (MT * SST * 4)           // 49664
#define C1_OFF STAGES                    // 64512
#define L1_SMEM STAGES                   // 64512 (S/xs/w1 alias stages)
#define L2_SMEM (C1_OFF + S_BYTES)       // 114176 -> 2 blocks/SM

__device__ float g_h1f[BATCH * HID];
__device__ float g_h2f[BATCH * HID];
__device__ bf16 g_h1hi[2][BATCH * HID];
__device__ bf16 g_h1lo[2][BATCH * HID];
__device__ bf16 g_h2hi[2][BATCH * HID];
__device__ bf16 g_h2lo[2][BATCH * HID];
__device__ bf16 g_whh1hi[G3 * HID];
__device__ bf16 g_whh1lo[G3 * HID];
__device__ bf16 g_wih2hi[G3 * HID];
__device__ bf16 g_wih2lo[G3 * HID];
__device__ bf16 g_whh2hi[G3 * HID];
__device__ bf16 g_whh2lo[G3 * HID];
__device__ float g_y[2][BATCH * NOUT];   // double-buffered y

__device__ __forceinline__ void cp16(uint32_t dst, const void* src) {
    asm volatile("cp.async.cg.shared.global [%0], [%1], 16;\n" ::"r"(dst), "l"(src));
}
__device__ __forceinline__ void ldsm4(uint32_t* r, uint32_t addr) {
    asm volatile("ldmatrix.sync.aligned.m8n8.x4.shared.b16 {%0,%1,%2,%3}, [%4];\n"
                 : "=r"(r[0]), "=r"(r[1]), "=r"(r[2]), "=r"(r[3]) : "r"(addr));
}
__device__ __forceinline__ void mma16816(float* c, const uint32_t* a, const uint32_t* b) {
    asm volatile(
        "mma.sync.aligned.m16n8k16.row.col.f32.bf16.bf16.f32 "
        "{%0,%1,%2,%3}, {%4,%5,%6,%7}, {%8,%9}, {%0,%1,%2,%3};\n"
        : "+f"(c[0]), "+f"(c[1]), "+f"(c[2]), "+f"(c[3])
        : "r"(a[0]), "r"(a[1]), "r"(a[2]), "r"(a[3]), "r"(b[0]), "r"(b[1]));
}

// K=512 GEMM mainloop (R8-proven): bf16 hi/lo 3-pass split, 32 chunks of K=16,
// 3-stage cp.async pipeline, 1 barrier/chunk, ldmatrix feed.
__device__ __forceinline__ void run_gemm(
    uint32_t smem_u32, int tid, int mBase, int jBase,
    const bf16* __restrict__ Ahi, const bf16* __restrict__ Alo,
    const bf16* __restrict__ Whi, const bf16* __restrict__ Wlo,
    float acc[2][6][4]) {
    const int lane = tid & 31;
    const int wid = tid >> 5;
    const int warpM = wid & 3;
    const int warpN = wid >> 2;

    const bf16* gsrc[4];
    uint32_t sdst[4];
    bool gval[4];
#pragma unroll
    for (int it = 0; it < 4; ++it) {
        int i = tid + it * 256;
        gval[it] = (i < 896);
        int u = gval[it] ? i : 0;
        if (u < 512) {
            const bf16* Ab = (u < 256) ? Ahi : Alo;
            uint32_t base = (u < 256) ? 0u : (uint32_t)AB;
            int rr = u & 255;
            int r = rr >> 1, c2 = rr & 1;
            gsrc[it] = Ab + (size_t)(mBase + r) * HID + c2 * 8;
            sdst[it] = base + r * (KPAD * 2) + c2 * 16;
        } else {
            int v = u - 512;
            const bf16* Wb = (v < 192) ? Whi : Wlo;
            uint32_t base = 2 * AB + ((v < 192) ? 0u : (uint32_t)BB);
            int rr = (v < 192) ? v : (v - 192);
            int r = rr >> 1, c2 = rr & 1;
            int wrow = (r >> 5) * HID + jBase + (r & 31);
            gsrc[it] = Wb + (size_t)wrow * HID + c2 * 8;
            sdst[it] = base + r * (KPAD * 2) + c2 * 16;
        }
    }

    uint32_t aoff[2], boff[3];
#pragma unroll
    for (int mt = 0; mt < 2; ++mt)
        aoff[mt] = (uint32_t)((warpM * 32 + mt * 16 + (lane & 15)) * KPAD + (lane >> 4) * 8);
#pragma unroll
    for (int p = 0; p < 3; ++p)
        boff[p] = (uint32_t)((warpN * 48 + p * 16 + (lane & 7) + ((lane & 16) ? 8 : 0)) * KPAD +
                             ((lane & 8) ? 8 : 0));

#pragma unroll
    for (int s = 0; s < 2; ++s) {
        uint32_t st = smem_u32 + s * STG;
        int k0 = s * KC;
#pragma unroll
        for (int it = 0; it < 4; ++it)
            if (gval[it]) cp16(st + sdst[it], gsrc[it] + k0);
        asm volatile("cp.async.commit_group;\n");
    }

#pragma unroll 1
    for (int c = 0; c < NCH; ++c) {
        if (c == NCH - 1)
            asm volatile("cp.async.wait_group 0;\n");
        else
            asm volatile("cp.async.wait_group 1;\n");
        __syncthreads();
        if (c + 2 < NCH) {
            uint32_t st = smem_u32 + ((c + 2) % NST) * STG;
            int k0 = (c + 2) * KC;
#pragma unroll
            for (int it = 0; it < 4; ++it)
                if (gval[it]) cp16(st + sdst[it], gsrc[it] + k0);
            asm volatile("cp.async.commit_group;\n");
        }
        uint32_t cur = smem_u32 + (c % NST) * STG;
        uint32_t sAh = cur;
        uint32_t sAl = cur + AB;
        uint32_t sBh = cur + 2 * AB;
        uint32_t sBl = cur + 2 * AB + BB;

        uint32_t a_frag[2][4], b_hi[6][2];
#pragma unroll
        for (int mt = 0; mt < 2; ++mt) ldsm4(&a_frag[mt][0], sAh + aoff[mt] * 2);
#pragma unroll
        for (int p = 0; p < 3; ++p) ldsm4(&b_hi[2 * p][0], sBh + boff[p] * 2);
#pragma unroll
        for (int mt = 0; mt < 2; ++mt)
#pragma unroll
            for (int nt = 0; nt < 6; ++nt) mma16816(acc[mt][nt], a_frag[mt], b_hi[nt]);
        uint32_t a_lo[2][4];
#pragma unroll
        for (int mt = 0; mt < 2; ++mt) ldsm4(&a_lo[mt][0], sAl + aoff[mt] * 2);
#pragma unroll
        for (int mt = 0; mt < 2; ++mt)
#pragma unroll
            for (int nt = 0; nt < 6; ++nt) mma16816(acc[mt][nt], a_lo[mt], b_hi[nt]);
        uint32_t b_lo[6][2];
#pragma unroll
        for (int p = 0; p < 3; ++p) ldsm4(&b_lo[2 * p][0], sBl + boff[p] * 2);
#pragma unroll
        for (int mt = 0; mt < 2; ++mt)
#pragma unroll
            for (int nt = 0; nt < 6; ++nt) mma16816(acc[mt][nt], a_frag[mt], b_lo[nt]);
    }
    __syncthreads();
}

__device__ __forceinline__ void stash_acc(float* S, float acc[2][6][4], int tid) {
    const int lane = tid & 31;
    const int wid = tid >> 5;
    const int warpM = wid & 3, warpN = wid >> 2;
    const int g = lane >> 2, q = lane & 3;
#pragma unroll
    for (int mt = 0; mt < 2; ++mt)
#pragma unroll
        for (int nt = 0; nt < 6; ++nt) {
            int r0 = warpM * 32 + mt * 16 + g;
            int cc = warpN * 48 + nt * 8 + q * 2;
            S[r0 * SST + cc] = acc[mt][nt][0];
            S[r0 * SST + cc + 1] = acc[mt][nt][1];
            S[(r0 + 8) * SST + cc] = acc[mt][nt][2];
            S[(r0 + 8) * SST + cc + 1] = acc[mt][nt][3];
        }
}

// layer1: gh1 = h1@Whh1^T (MMA), gi1 from x=[y,cmd] (K=8 scalar), GRU.
// Blocks with blockIdx.y==0 also pre-write bias into out[:, t, :] and ybuf_nxt
// (l2's y-atomics accumulate on top; kernel ordering guarantees visibility).
__global__ void __launch_bounds__(256, 2) l1_kernel(
    const bf16* __restrict__ Ahi, const bf16* __restrict__ Alo,
    const bf16* __restrict__ Whi, const bf16* __restrict__ Wlo,
    const float* __restrict__ bhh, float* __restrict__ hf,
    bf16* __restrict__ out_hi, bf16* __restrict__ out_lo,
    const float* __restrict__ ybuf_cur, const float* __restrict__ cmd_t,
    const float* __restrict__ Wih1, const float* __restrict__ bih,
    const float* __restrict__ bout, float* __restrict__ ybuf_nxt,
    float* __restrict__ out, int t) {
    extern __shared__ char smem[];
    uint32_t smem_u32 = (uint32_t)__cvta_generic_to_shared(smem);
    const int tid = threadIdx.x;
    const int mBase = blockIdx.x * MT;
    const int jBase = blockIdx.y * JT;

    // y bias pre-init (once per batch-row tile)
    if (blockIdx.y == 0) {
        for (int i = tid; i < MT * NOUT; i += 256) {
            int r = i / NOUT, o = i % NOUT;
            float v = bout[o];
            ybuf_nxt[(mBase + r) * NOUT + o] = v;
            out[(size_t)(mBase + r) * (T_STEPS * NOUT) + t * NOUT + o] = v;
        }
    }

    float acc[2][6][4];
#pragma unroll
    for (int a = 0; a < 2; ++a)
#pragma unroll
        for (int b = 0; b < 6; ++b)
#pragma unroll
            for (int e = 0; e < 4; ++e) acc[a][b][e] = 0.f;

    run_gemm(smem_u32, tid, mBase, jBase, Ahi, Alo, Whi, Wlo, acc);

    float* S = (float*)smem;
    stash_acc(S, acc, tid);
    float* xs = (float*)(smem + S_BYTES);         // [128][8]
    float* w1 = (float*)(smem + S_BYTES + 4096);  // [96][8]
    for (int i = tid; i < MT * 8; i += 256) {
        int r = i >> 3, k = i & 7;
        xs[i] = (k < NOUT) ? ybuf_cur[(mBase + r) * NOUT + k]
                           : cmd_t[(size_t)(mBase + r) * NCMD + (k - NOUT)];
    }
    for (int i = tid; i < NT * 8; i += 256) {
        int n = i >> 3, k = i & 7;
        int wr = (n >> 5) * HID + jBase + (n & 31);
        w1[i] = Wih1[wr * 8 + k];
    }
    __syncthreads();

    for (int i = tid; i < MT * JT; i += 256) {
        int jj = i & 31, r = i >> 5;
        int b = mBase + r;
        int j = jBase + jj;
        float ghr = S[r * SST + jj] + bhh[j];
        float ghz = S[r * SST + 32 + jj] + bhh[HID + j];
        float ghn = S[r * SST + 64 + jj] + bhh[2 * HID + j];
        float gir = bih[j], giz = bih[HID + j], gin = bih[2 * HID + j];
#pragma unroll
        for (int k = 0; k < 8; ++k) {
            float xv = xs[r * 8 + k];
            gir += xv * w1[jj * 8 + k];
            giz += xv * w1[(32 + jj) * 8 + k];
            gin += xv * w1[(64 + jj) * 8 + k];
        }
        float rg = 1.f / (1.f + __expf(-(gir + ghr)));
        float zg = 1.f / (1.f + __expf(-(giz + ghz)));
        float ng = tanhf(gin + rg * ghn);
        float hold = hf[(size_t)b * HID + j];
        float hnew = (1.f - zg) * ng + zg * hold;
        hf[(size_t)b * HID + j] = hnew;
        bf16 h = __float2bfloat16(hnew);
        out_hi[(size_t)b * HID + j] = h;
        out_lo[(size_t)b * HID + j] = __float2bfloat16(hnew - __bfloat162float(h));
    }
}

// layer2 (merged): gi2 GEMM -> smem C1, gh2 GEMM, GRU update, and fused y
// partials: per (row, o) warp-shuffle reduce over this block's 32 j's, then
// atomicAdd into ybuf_nxt and out (bias pre-written by l1).
__global__ void __launch_bounds__(256, 2) l2_kernel(
    const bf16* __restrict__ A1hi, const bf16* __restrict__ A1lo,  // h1_new
    const bf16* __restrict__ Wihi, const bf16* __restrict__ Wilo,  // W_ih2
    const bf16* __restrict__ A2hi, const bf16* __restrict__ A2lo,  // h2_old
    const bf16* __restrict__ Whhi, const bf16* __restrict__ Whlo,  // W_hh2
    const float* __restrict__ bih, const float* __restrict__ bhh,
    float* __restrict__ hf, bf16* __restrict__ out_hi, bf16* __restrict__ out_lo,
    const float* __restrict__ Wout, float* __restrict__ ybuf_nxt,
    float* __restrict__ out, int t) {
    extern __shared__ char smem[];
    uint32_t smem_u32 = (uint32_t)__cvta_generic_to_shared(smem);
    const int tid = threadIdx.x;
    const int lane = tid & 31;
    const int mBase = blockIdx.x * MT;
    const int jBase = blockIdx.y * JT;

    float acc[2][6][4];
#pragma unroll
    for (int a = 0; a < 2; ++a)
#pragma unroll
        for (int b = 0; b < 6; ++b)
#pragma unroll
            for (int e = 0; e < 4; ++e) acc[a][b][e] = 0.f;

    run_gemm(smem_u32, tid, mBase, jBase, A1hi, A1lo, Wihi, Wilo, acc);
    float* C1 = (float*)(smem + C1_OFF);
    stash_acc(C1, acc, tid);
    __syncthreads();

#pragma unroll
    for (int a = 0; a < 2; ++a)
#pragma unroll
        for (int b = 0; b < 6; ++b)
#pragma unroll
            for (int e = 0; e < 4; ++e) acc[a][b][e] = 0.f;
    run_gemm(smem_u32, tid, mBase, jBase, A2hi, A2lo, Whhi, Whlo, acc);
    float* S = (float*)smem;
    stash_acc(S, acc, tid);
    __syncthreads();

    // Wout columns for this thread's fixed jj (jj = tid&31 for every iter)
    const int jj = tid & 31;
    const int j0 = jBase + jj;
    float wo[NOUT];
#pragma unroll
    for (int o = 0; o < NOUT; ++o) wo[o] = Wout[o * HID + j0];

    for (int i = tid; i < MT * JT; i += 256) {
        int r = i >> 5;  // same jj each iter; warp handles one row per iter
        int b = mBase + r;
        int j = jBase + jj;
        float ghr = S[r * SST + jj] + bhh[j];
        float ghz = S[r * SST + 32 + jj] + bhh[HID + j];
        float ghn = S[r * SST + 64 + jj] + bhh[2 * HID + j];
        float gir = C1[r * SST + jj] + bih[j];
        float giz = C1[r * SST + 32 + jj] + bih[HID + j];
        float gin = C1[r * SST + 64 + jj] + bih[2 * HID + j];
        float rg = 1.f / (1.f + __expf(-(gir + ghr)));
        float zg = 1.f / (1.f + __expf(-(giz + ghz)));
        float ng = tanhf(gin + rg * ghn);
        float hold = hf[(size_t)b * HID + j];
        float hnew = (1.f - zg) * ng + zg * hold;
        hf[(size_t)b * HID + j] = hnew;
        bf16 h = __float2bfloat16(hnew);
        out_hi[(size_t)b * HID + j] = h;
        out_lo[(size_t)b * HID + j] = __float2bfloat16(hnew - __bfloat162float(h));

        // y partial: reduce hnew*wo over the warp's 32 j's (one row per iter)
#pragma unroll
        for (int o = 0; o < NOUT; ++o) {
            float pv = hnew * wo[o];
#pragma unroll
            for (int off = 16; off; off >>= 1)
                pv += __shfl_down_sync(0xffffffffu, pv, off);
            if (lane == 0) {
                atomicAdd(&ybuf_nxt[b * NOUT + o], pv);
                atomicAdd(&out[(size_t)b * (T_STEPS * NOUT) + t * NOUT + o], pv);
            }
        }
    }
}

// single fused init: weight hi/lo splits + state splits + y copy (1 launch)
__global__ void init_kernel(
    const float* __restrict__ Whh1, const float* __restrict__ Wih2,
    const float* __restrict__ Whh2, const float* __restrict__ h01,
    const float* __restrict__ h02, const float* __restrict__ y0,
    bf16* __restrict__ whh1hi, bf16* __restrict__ whh1lo,
    bf16* __restrict__ wih2hi, bf16* __restrict__ wih2lo,
    bf16* __restrict__ whh2hi, bf16* __restrict__ whh2lo,
    float* __restrict__ h1f, float* __restrict__ h2f,
    bf16* __restrict__ h1hi, bf16* __restrict__ h1lo,
    bf16* __restrict__ h2hi, bf16* __restrict__ h2lo,
    float* __restrict__ ybuf0) {
    int i = blockIdx.x * blockDim.x + threadIdx.x;
    const int NW = G3 * HID;
    const int NS = BATCH * HID;
    if (i < NW) {
        float v = Whh1[i];
        bf16 h = __float2bfloat16(v);
        whh1hi[i] = h;
        whh1lo[i] = __float2bfloat16(v - __bfloat162float(h));
        v = Wih2[i];
        h = __float2bfloat16(v);
        wih2hi[i] = h;
        wih2lo[i] = __float2bfloat16(v - __bfloat162float(h));
        v = Whh2[i];
        h = __float2bfloat16(v);
        whh2hi[i] = h;
        whh2lo[i] = __float2bfloat16(v - __bfloat162float(h));
    }
    if (i < NS) {
        float v = h01[i];
        h1f[i] = v;
        bf16 h = __float2bfloat16(v);
        h1hi[i] = h;
        h1lo[i] = __float2bfloat16(v - __bfloat162float(h));
        v = h02[i];
        h2f[i] = v;
        h = __float2bfloat16(v);
        h2hi[i] = h;
        h2lo[i] = __float2bfloat16(v - __bfloat162float(h));
    }
    if (i < BATCH * NOUT) ybuf0[i] = y0[i];
}

extern "C" void kernel_launch(void* const* d_in, const int* in_sizes, int n_in,
                              void* d_out, int out_size) {
    (void)in_sizes; (void)n_in; (void)out_size;
    const float* cmds = (const float*)d_in[1];
    const float* y0 = (const float*)d_in[2];
    const float* h01 = (const float*)d_in[3];
    const float* h02 = (const float*)d_in[4];
    const float* Wih1 = (const float*)d_in[5];
    const float* Whh1 = (const float*)d_in[6];
    const float* bih1 = (const float*)d_in[7];
    const float* bhh1 = (const float*)d_in[8];
    const float* Wih2 = (const float*)d_in[9];
    const float* Whh2 = (const float*)d_in[10];
    const float* bih2 = (const float*)d_in[11];
    const float* bhh2 = (const float*)d_in[12];
    const float* Wout = (const float*)d_in[13];
    const float* bout = (const float*)d_in[14];
    float* out = (float*)d_out;

    void* p;
    float *h1f, *h2f, *ybuf;
    bf16 *h1hi, *h1lo, *h2hi, *h2lo;
    bf16 *whh1hi, *whh1lo, *wih2hi, *wih2lo, *whh2hi, *whh2lo;
    cudaGetSymbolAddress(&p, g_h1f); h1f = (float*)p;
    cudaGetSymbolAddress(&p, g_h2f); h2f = (float*)p;
    cudaGetSymbolAddress(&p, g_y); ybuf = (float*)p;
    cudaGetSymbolAddress(&p, g_h1hi); h1hi = (bf16*)p;
    cudaGetSymbolAddress(&p, g_h1lo); h1lo = (bf16*)p;
    cudaGetSymbolAddress(&p, g_h2hi); h2hi = (bf16*)p;
    cudaGetSymbolAddress(&p, g_h2lo); h2lo = (bf16*)p;
    cudaGetSymbolAddress(&p, g_whh1hi); whh1hi = (bf16*)p;
    cudaGetSymbolAddress(&p, g_whh1lo); whh1lo = (bf16*)p;
    cudaGetSymbolAddress(&p, g_wih2hi); wih2hi = (bf16*)p;
    cudaGetSymbolAddress(&p, g_wih2lo); wih2lo = (bf16*)p;
    cudaGetSymbolAddress(&p, g_whh2hi); whh2hi = (bf16*)p;
    cudaGetSymbolAddress(&p, g_whh2lo); whh2lo = (bf16*)p;

    cudaFuncSetAttribute(l1_kernel, cudaFuncAttributeMaxDynamicSharedMemorySize, L1_SMEM);
    cudaFuncSetAttribute(l2_kernel, cudaFuncAttributeMaxDynamicSharedMemorySize, L2_SMEM);

    const int NS = BATCH * HID;
    init_kernel<<<(NS + 255) / 256, 256>>>(
        Whh1, Wih2, Whh2, h01, h02, y0,
        whh1hi, whh1lo, wih2hi, wih2lo, whh2hi, whh2lo,
        h1f, h2f, h1hi, h1lo, h2hi, h2lo, ybuf);

    dim3 grid(BATCH / MT, HID / JT);
    for (int t = 0; t < T_STEPS; ++t) {
        int cur = t & 1, nxt = (t + 1) & 1;
        bf16* h1hi_c = h1hi + (size_t)cur * NS;
        bf16* h1lo_c = h1lo + (size_t)cur * NS;
        bf16* h1hi_n = h1hi + (size_t)nxt * NS;
        bf16* h1lo_n = h1lo + (size_t)nxt * NS;
        bf16* h2hi_c = h2hi + (size_t)cur * NS;
        bf16* h2lo_c = h2lo + (size_t)cur * NS;
        bf16* h2hi_n = h2hi + (size_t)nxt * NS;
        bf16* h2lo_n = h2lo + (size_t)nxt * NS;
        float* ybuf_cur = ybuf + (size_t)cur * (BATCH * NOUT);
        float* ybuf_nxt = ybuf + (size_t)nxt * (BATCH * NOUT);
        const float* cmd_t = cmds + (size_t)t * BATCH * NCMD;

        l1_kernel<<<grid, 256, L1_SMEM>>>(
            h1hi_c, h1lo_c, whh1hi, whh1lo, bhh1,
            h1f, h1hi_n, h1lo_n, ybuf_cur, cmd_t, Wih1, bih1,
            bout, ybuf_nxt, out, t);
        l2_kernel<<<grid, 256, L2_SMEM>>>(
            h1hi_n, h1lo_n, wih2hi, wih2lo,
            h2hi_c, h2lo_c, whh2hi, whh2lo,
            bih2, bhh2, h2f, h2hi_n, h2lo_n,
            Wout, ybuf_nxt, out, t);
    }
}